// round 4
// baseline (speedup 1.0000x reference)
#include <cuda_runtime.h>

// SceneEngine: closed-form subset-sum factorization.
//   sum over non-empty subsets of exp(Σ_s exist[s,bit_s]) = Π_s(e0+e1) − Π_s e0
//   number_prob  -> elementary symmetric polynomial DP on Π_s(e0 + t·e1)
//   attr prob[d] -> (Π_s(e0 + e1·exp(a[s,d])) − Π_s e0) / Z
//
// R3 layout: block = 128 threads = 32 pairs.
//   Stage all inputs for the block's 32 pairs into SMEM with coalesced
//   float4 loads, then 4 role warps (one per SMSP) compute from SMEM:
//     w0: exist_prob + symmetric DP + number_prob
//     w1: type(5)   w2: size(6)   w3: color(10)
//   lane = local pair; k = lane&15; rule-min via 8-lane shfl groups.

constexpr int NS = 9;

constexpr int OFF_EXIST  = 0;
constexpr int OFF_NUM    = 73728;
constexpr int OFF_TYPE   = 110592;
constexpr int OFF_NTYPE  = 135168;
constexpr int OFF_RTYPE  = 145408;
constexpr int OFF_SIZE   = 145664;
constexpr int OFF_NSIZE  = 174336;
constexpr int OFF_RSIZE  = 186624;
constexpr int OFF_COLOR  = 186880;
constexpr int OFF_NCOLOR = 231936;
constexpr int OFF_RCOLOR = 252416;

// per-block (32-pair) segment sizes in floats
constexpr int SEG_EX = 32 * 18;   // 576
constexpr int SEG_TY = 32 * 45;   // 1440
constexpr int SEG_SI = 32 * 54;   // 1728
constexpr int SEG_CO = 32 * 90;   // 2880

#define BIGF 3.402823466e+38f

__device__ __forceinline__ void copy4(float* __restrict__ dst,
                                      const float* __restrict__ src,
                                      int n4, int t)
{
    float4* __restrict__ d = (float4*)dst;
    const float4* __restrict__ s = (const float4*)src;
    for (int i = t; i < n4; i += 128) d[i] = s[i];
}

// min over the 8 lanes of each aligned 8-lane subgroup
__device__ __forceinline__ float min8(float v)
{
#pragma unroll
    for (int off = 4; off >= 1; off >>= 1)
        v = fminf(v, __shfl_xor_sync(0xFFFFFFFFu, v, off));
    return v;
}

// exps of the exist row for local pair `lane` from SMEM
__device__ __forceinline__ void load_exist(const float* __restrict__ s_ex,
                                           int lane, float e0[NS], float e1[NS])
{
    const float* r = s_ex + lane * 18;
#pragma unroll
    for (int s = 0; s < NS; s++) {
        e0[s] = __expf(r[2 * s + 0]);
        e1[s] = __expf(r[2 * s + 1]);
    }
}

template <int D>
__device__ __forceinline__ void attr_role(
    const float* __restrict__ s_attr,   // SMEM segment [32][9][D]
    int lane, int pair, int b, int k,
    float* __restrict__ out,
    const float* __restrict__ s_ex,
    int off_prob, int off_norm, int off_rule)
{
    float e0[NS], e1[NS];
    load_exist(s_ex, lane, e0, e1);

    float S0 = 1.0f, Zp = 1.0f;
#pragma unroll
    for (int s = 0; s < NS; s++) { S0 *= e0[s]; Zp *= (e0[s] + e1[s]); }
    float invZ = __fdividef(1.0f, Zp - S0);

    const float* __restrict__ a = s_attr + lane * NS * D;
    float p[D];
#pragma unroll
    for (int d = 0; d < D; d++) p[d] = 1.0f;
#pragma unroll
    for (int s = 0; s < NS; s++) {
#pragma unroll
        for (int d = 0; d < D; d++)
            p[d] *= fmaf(e1[s], __expf(a[s * D + d]), e0[s]);
    }

    float sum = 0.0f;
#pragma unroll
    for (int d = 0; d < D; d++) {
        p[d] = (p[d] - S0) * invZ;
        sum += p[d];
    }
    float nic = fminf(sum, 1.0f);

    float* __restrict__ op = out + off_prob + (size_t)pair * (D + 1);
#pragma unroll
    for (int d = 0; d < D; d++) op[d] = p[d];
    op[D] = 1.0f - nic;

    if (k < 8) {
        float inv = __fdividef(1.0f, sum);
        float* __restrict__ on = out + off_norm + (size_t)(b * 8 + k) * D;
#pragma unroll
        for (int d = 0; d < D; d++) on[d] = p[d] * inv;
    }

    float v = (k < 8) ? nic : BIGF;
    v = min8(v);
    if (k == 0) out[off_rule + b] = v;   // lanes 0 and 16 (different b)
}

__global__ __launch_bounds__(128)
void scene_engine_kernel(const float* __restrict__ exist,
                         const float* __restrict__ typ,
                         const float* __restrict__ siz,
                         const float* __restrict__ col,
                         float* __restrict__ out)
{
    __shared__ float s_ex[SEG_EX];
    __shared__ float s_ty[SEG_TY];
    __shared__ float s_si[SEG_SI];
    __shared__ float s_co[SEG_CO];

    int t = threadIdx.x;
    int blk = blockIdx.x;

    // coalesced staging: 1656 float4 across 128 threads
    copy4(s_ex, exist + (size_t)blk * SEG_EX, SEG_EX / 4, t);
    copy4(s_ty, typ   + (size_t)blk * SEG_TY, SEG_TY / 4, t);
    copy4(s_si, siz   + (size_t)blk * SEG_SI, SEG_SI / 4, t);
    copy4(s_co, col   + (size_t)blk * SEG_CO, SEG_CO / 4, t);
    __syncthreads();

    int w = t >> 5;
    int lane = t & 31;
    int pair = blk * 32 + lane;
    int b = pair >> 4;
    int k = lane & 15;

    if (w == 0) {
        // exist_prob + symmetric-poly DP + number_prob
        float e0[NS], e1[NS];
        load_exist(s_ex, lane, e0, e1);

        float* __restrict__ oex = out + OFF_EXIST + (size_t)pair * 18;
#pragma unroll
        for (int s = 0; s < NS; s++) {
            float2 v = make_float2(e0[s], e1[s]);
            ((float2*)oex)[s] = v;
        }

        float c[NS + 1];
        c[0] = 1.0f;
#pragma unroll
        for (int i = 1; i <= NS; i++) c[i] = 0.0f;
#pragma unroll
        for (int s = 0; s < NS; s++) {
#pragma unroll
            for (int j = NS; j >= 1; j--)
                c[j] = fmaf(c[j], e0[s], c[j - 1] * e1[s]);
            c[0] *= e0[s];
        }
        float Z = 0.0f;
#pragma unroll
        for (int j = 1; j <= NS; j++) Z += c[j];
        float invZ = __fdividef(1.0f, Z);

        float* __restrict__ onum = out + OFF_NUM + (size_t)pair * NS;
#pragma unroll
        for (int n = 0; n < NS; n++) onum[n] = c[n + 1] * invZ;
    } else if (w == 1) {
        attr_role<5>(s_ty, lane, pair, b, k, out, s_ex, OFF_TYPE, OFF_NTYPE, OFF_RTYPE);
    } else if (w == 2) {
        attr_role<6>(s_si, lane, pair, b, k, out, s_ex, OFF_SIZE, OFF_NSIZE, OFF_RSIZE);
    } else {
        attr_role<10>(s_co, lane, pair, b, k, out, s_ex, OFF_COLOR, OFF_NCOLOR, OFF_RCOLOR);
    }
}

extern "C" void kernel_launch(void* const* d_in, const int* in_sizes, int n_in,
                              void* d_out, int out_size)
{
    const float* exist = (const float*)d_in[0];
    const float* typ   = (const float*)d_in[1];
    const float* siz   = (const float*)d_in[2];
    const float* col   = (const float*)d_in[3];
    float* out = (float*)d_out;

    // 128 blocks × 128 threads; one block per SM wave, 32 pairs per block.
    scene_engine_kernel<<<128, 128>>>(exist, typ, siz, col, out);
}